// round 14
// baseline (speedup 1.0000x reference)
#include <cuda_runtime.h>
#include <cstdint>

// GHMRankingLoss, fused single kernel: DUAL memory path (LDG + TMA ring).
//
//   result = (1/N) * sum_{b=5..9} max(cnt_b,1)^-0.75 * S_b   (bins 0-4: loss==0)
// u = -t*diff; x = u*(2-t) == 2u + diff (t^2==1). Cumulative register tallies
// C_k = sum_{x>=T_k} u, N_k = #{x>=T_k}, T = {0, ln(6/4), ln(7/3), ln(8/2),
// ln(9/1)}; per-bin values by differencing. FSET -> {0,1}, FFMA/FADD accum.
//
// Why dual-path: every LDG-only variant pinned at ~30 B/cyc/SM -- the L1tex
// demand-return queue (~248 wavefronts ~= 31KB in flight) is the per-SM cap.
// TMA bulk copies (DRAM->SMEM) use a different queue. Each CTA-round covers
// 4096 floats/array: first 2048 via 6 front-batched LDG.128 (+L2 prefetch),
// second 2048 via one 8KB cp.async.bulk per array into a 3-stage smem ring
// filled by a dedicated producer warp. Consumers overlap: issue LDGs, consume
// the smem half while the LDGs are in flight, then consume the LDG half.

#define NTC  256              // consumer threads (8 warps)
#define NT   288              // + 1 producer warp
#define NB   444              // 3 CTAs/SM * 148 SMs
#define K    5
#define PD   2                // L2-prefetch distance for the LDG half (rounds)
#define TILE_F 2048           // floats per array per stage (= 8KB)
#define STB  8192             // stage bytes per array
#define ST   3                // ring stages: 3 * 3 * 8KB = 72KB dynamic smem
#define DSMEM (ST * 3 * STB)
#define ROUND4 (NB * 1024)    // float4 per round, all CTAs, per array

__device__ float2 g_part[K * NB];   // k-major: [k][block] = (C_k, N_k)
__device__ unsigned int g_ticket;   // zero at load; last block resets

__device__ __forceinline__ uint32_t smem_u32(const void* p) {
    return (uint32_t)__cvta_generic_to_shared(p);
}
__device__ __forceinline__ void pf_l2(const void* p) {
    asm volatile("cp.async.bulk.prefetch.L2.global [%0], %1;"
                 :: "l"(p), "r"(4096) : "memory");
}
__device__ __forceinline__ void bulk_ld(uint32_t dst, const float* src, uint32_t mbar) {
    asm volatile(
        "cp.async.bulk.shared::cta.global.mbarrier::complete_tx::bytes [%0], [%1], %2, [%3];"
        :: "r"(dst), "l"(src), "r"(STB), "r"(mbar) : "memory");
}
__device__ __forceinline__ void mbar_init(uint32_t mbar, uint32_t cnt) {
    asm volatile("mbarrier.init.shared.b64 [%0], %1;" :: "r"(mbar), "r"(cnt) : "memory");
}
__device__ __forceinline__ void mbar_expect(uint32_t mbar, uint32_t bytes) {
    asm volatile("mbarrier.arrive.expect_tx.shared.b64 _, [%0], %1;"
                 :: "r"(mbar), "r"(bytes) : "memory");
}
__device__ __forceinline__ void mbar_arrive(uint32_t mbar) {
    asm volatile("mbarrier.arrive.shared.b64 _, [%0];" :: "r"(mbar) : "memory");
}
__device__ __forceinline__ void mbar_wait(uint32_t mbar, uint32_t parity) {
    asm volatile(
        "{\n\t"
        ".reg .pred P;\n\t"
        "WAIT_%=: mbarrier.try_wait.parity.acquire.cta.shared::cta.b64 P, [%0], %1, 0x989680;\n\t"
        "@P bra.uni DONE_%=;\n\t"
        "bra.uni WAIT_%=;\n\t"
        "DONE_%=:\n\t"
        "}"
        :: "r"(mbar), "r"(parity) : "memory");
}

__device__ __forceinline__ float fset_ge(float x, float T) {
    float r;
    asm("set.ge.f32.f32 %0, %1, %2;" : "=f"(r) : "f"(x), "f"(T));
    return r;   // 1.0f if x >= T else 0.0f
}

__device__ __forceinline__ void ghm_accum(
    float& c0, float& c1, float& c2, float& c3, float& c4,
    float& n0, float& n1, float& n2, float& n3, float& n4,
    float a, float b, float t) {
    float diff = a - b;
    float u = -t * diff;              // == loss whenever u >= 0
    float x = fmaf(2.0f, u, diff);    // == u*(2-t) since t*t == 1
    float r0 = fset_ge(x, 0.0f);
    float r1 = fset_ge(x, 0.40546511f);   // ln(6/4)
    float r2 = fset_ge(x, 0.84729786f);   // ln(7/3)
    float r3 = fset_ge(x, 1.38629436f);   // ln(8/2)
    float r4 = fset_ge(x, 2.19722458f);   // ln(9/1)
    c0 = fmaf(r0, u, c0);  n0 += r0;
    c1 = fmaf(r1, u, c1);  n1 += r1;
    c2 = fmaf(r2, u, c2);  n2 += r2;
    c3 = fmaf(r3, u, c3);  n3 += r3;
    c4 = fmaf(r4, u, c4);  n4 += r4;
}
#define ACC(av, bv, tv) ghm_accum(c0,c1,c2,c3,c4,n0,n1,n2,n3,n4, av, bv, tv)

__global__ void __launch_bounds__(NT, 3)
ghm_fused_k(const float* __restrict__ o1,
            const float* __restrict__ o2,
            const float* __restrict__ tg,
            float* __restrict__ out,
            int n) {
    extern __shared__ __align__(128) float dsm[];   // [ST][3][TILE_F]
    __shared__ unsigned long long full_b[ST], empty_b[ST];

    const int tid = threadIdx.x;
    const int bid = blockIdx.x;

    uint32_t fullm[ST], emptym[ST];
    #pragma unroll
    for (int s = 0; s < ST; s++) {
        fullm[s]  = smem_u32(&full_b[s]);
        emptym[s] = smem_u32(&empty_b[s]);
    }
    if (tid == 0) {
        #pragma unroll
        for (int s = 0; s < ST; s++) {
            mbar_init(fullm[s], 1);      // producer complete_tx flips it
            mbar_init(emptym[s], NTC);   // all consumers release
        }
    }
    __syncthreads();

    const int n4e     = n >> 2;
    const int nrounds = n4e / ROUND4;

    float c0 = 0.f, c1 = 0.f, c2 = 0.f, c3 = 0.f, c4 = 0.f;
    float n0 = 0.f, n1 = 0.f, n2 = 0.f, n3 = 0.f, n4 = 0.f;

    const float4* __restrict__ A = (const float4*)o1;
    const float4* __restrict__ B = (const float4*)o2;
    const float4* __restrict__ T = (const float4*)tg;

    if (tid >= NTC) {
        // ---- producer warp: elected thread streams the TMA half ----
        if (tid == NTC) {
            int slot = 0, phase = 1;   // first ST empty-waits pass immediately
            for (int r = 0; r < nrounds; r++) {
                mbar_wait(emptym[slot], phase);
                size_t fbase = ((size_t)r * ROUND4 + (size_t)bid * 1024) * 4 + 2048;
                float* stg = dsm + slot * 3 * TILE_F;
                mbar_expect(fullm[slot], 3 * STB);
                bulk_ld(smem_u32(stg),              o1 + fbase, fullm[slot]);
                bulk_ld(smem_u32(stg + TILE_F),     o2 + fbase, fullm[slot]);
                bulk_ld(smem_u32(stg + 2 * TILE_F), tg + fbase, fullm[slot]);
                if (++slot == ST) { slot = 0; phase ^= 1; }
            }
        }
    } else {
        // ---- 8 consumer warps: LDG half + smem half per round ----
        // warm the L2 window for the LDG chunks of the first PD rounds
        if (tid == 0) {
            for (int d = 0; d < PD && d < nrounds; d++) {
                const float4* pa = A + (size_t)d * ROUND4 + bid * 1024;
                const float4* pb = B + (size_t)d * ROUND4 + bid * 1024;
                const float4* pt = T + (size_t)d * ROUND4 + bid * 1024;
                pf_l2(pa); pf_l2(pa + 256);
                pf_l2(pb); pf_l2(pb + 256);
                pf_l2(pt); pf_l2(pt + 256);
            }
        }

        int slot = 0, phase = 0;
        for (int r = 0; r < nrounds; r++) {
            size_t g = (size_t)r * ROUND4 + (size_t)bid * 1024;

            if (tid == 0 && r + PD < nrounds) {
                size_t pg = g + (size_t)PD * ROUND4;
                pf_l2(A + pg); pf_l2(A + pg + 256);
                pf_l2(B + pg); pf_l2(B + pg + 256);
                pf_l2(T + pg); pf_l2(T + pg + 256);
            }

            // issue the LDG half (front-batched, consumed last)
            float4 a0 = __ldcs(A + g + tid);
            float4 b0 = __ldcs(B + g + tid);
            float4 t0 = __ldcs(T + g + tid);
            float4 a1 = __ldcs(A + g + 256 + tid);
            float4 b1 = __ldcs(B + g + 256 + tid);
            float4 t1 = __ldcs(T + g + 256 + tid);

            // consume the smem half while LDGs are in flight
            mbar_wait(fullm[slot], phase);
            const float4* sa = (const float4*)(dsm + slot * 3 * TILE_F);
            const float4* sb = (const float4*)(dsm + slot * 3 * TILE_F + TILE_F);
            const float4* st = (const float4*)(dsm + slot * 3 * TILE_F + 2 * TILE_F);
            float4 sa0 = sa[tid * 2], sa1 = sa[tid * 2 + 1];
            float4 sb0 = sb[tid * 2], sb1 = sb[tid * 2 + 1];
            float4 st0 = st[tid * 2], st1 = st[tid * 2 + 1];
            mbar_arrive(emptym[slot]);   // release before computing
            ACC(sa0.x, sb0.x, st0.x);  ACC(sa0.y, sb0.y, st0.y);
            ACC(sa0.z, sb0.z, st0.z);  ACC(sa0.w, sb0.w, st0.w);
            ACC(sa1.x, sb1.x, st1.x);  ACC(sa1.y, sb1.y, st1.y);
            ACC(sa1.z, sb1.z, st1.z);  ACC(sa1.w, sb1.w, st1.w);

            // consume the LDG half
            ACC(a0.x, b0.x, t0.x);  ACC(a0.y, b0.y, t0.y);
            ACC(a0.z, b0.z, t0.z);  ACC(a0.w, b0.w, t0.w);
            ACC(a1.x, b1.x, t1.x);  ACC(a1.y, b1.y, t1.y);
            ACC(a1.z, b1.z, t1.z);  ACC(a1.w, b1.w, t1.w);

            if (++slot == ST) { slot = 0; phase ^= 1; }
        }

        // tail beyond full rounds: plain grid-stride LDG (consumers only)
        for (int i = nrounds * ROUND4 + bid * NTC + tid; i < n4e; i += NB * NTC) {
            float4 a = __ldcs(A + i);
            float4 b = __ldcs(B + i);
            float4 t = __ldcs(T + i);
            ACC(a.x, b.x, t.x);  ACC(a.y, b.y, t.y);
            ACC(a.z, b.z, t.z);  ACC(a.w, b.w, t.w);
        }
        // scalar tail (n not multiple of 4)
        for (int j = (n4e << 2) + bid * NTC + tid; j < n; j += NB * NTC)
            ACC(o1[j], o2[j], tg[j]);
    }

    // ---- block reduce: warp shfl, then cross-warp via smem (9 warps) ----
    float cs[K] = {c0, c1, c2, c3, c4};
    float ns[K] = {n0, n1, n2, n3, n4};
    #pragma unroll
    for (int off = 16; off; off >>= 1) {
        #pragma unroll
        for (int k = 0; k < K; k++) {
            cs[k] += __shfl_down_sync(0xffffffff, cs[k], off);
            ns[k] += __shfl_down_sync(0xffffffff, ns[k], off);
        }
    }

    __shared__ float sC[K][NT / 32], sN[K][NT / 32];
    const int warp = tid >> 5, lane = tid & 31;
    if (lane == 0) {
        #pragma unroll
        for (int k = 0; k < K; k++) { sC[k][warp] = cs[k]; sN[k][warp] = ns[k]; }
    }
    __syncthreads();

    if (tid < K) {
        float c = 0.f, nn = 0.f;
        #pragma unroll
        for (int w = 0; w < NT / 32; w++) { c += sC[tid][w]; nn += sN[tid][w]; }
        g_part[tid * NB + bid] = make_float2(c, nn);
    }

    // ---- ticket: last block finalizes ----
    __shared__ bool isLast;
    __threadfence();
    if (tid == 0) {
        unsigned int v = atomicAdd(&g_ticket, 1u);
        isLast = (v == NB - 1);
    }
    __syncthreads();
    if (!isLast) return;

    __shared__ double ss[K], cc[K];
    if (warp < K) {
        double s = 0.0, c = 0.0;
        for (int j = lane; j < NB; j += 32) {
            float2 p = g_part[warp * NB + j];   // L2-resident
            s += (double)p.x;
            c += (double)p.y;
        }
        #pragma unroll
        for (int off = 16; off; off >>= 1) {
            s += __shfl_down_sync(0xffffffff, s, off);
            c += __shfl_down_sync(0xffffffff, c, off);
        }
        if (lane == 0) { ss[warp] = s; cc[warp] = c; }
    }
    __syncthreads();

    if (tid == 0) {
        double acc = 0.0;
        #pragma unroll
        for (int m = 0; m < K; m++) {
            double Sm  = ss[m] - ((m + 1 < K) ? ss[m + 1] : 0.0);  // bin 5+m loss sum
            double cnt = cc[m] - ((m + 1 < K) ? cc[m + 1] : 0.0);  // bin 5+m count
            double tot = cnt < 1.0 ? 1.0 : cnt;                    // clamp(min=1)
            acc += pow(tot, -0.75) * Sm;                           // w = tot^-alpha
        }
        out[0] = (float)(acc / (double)n);
        g_ticket = 0;                                               // graph-replay safe
    }
}

extern "C" void kernel_launch(void* const* d_in, const int* in_sizes, int n_in,
                              void* d_out, int out_size) {
    const float* o1 = (const float*)d_in[0];
    const float* o2 = (const float*)d_in[1];
    const float* tg = (const float*)d_in[2];
    float* out = (float*)d_out;
    int n = in_sizes[0];

    // idempotent; no allocation. Needed for 72KB dynamic smem.
    cudaFuncSetAttribute(ghm_fused_k, cudaFuncAttributeMaxDynamicSharedMemorySize, DSMEM);
    ghm_fused_k<<<NB, NT, DSMEM>>>(o1, o2, tg, out, n);
}

// round 15
// speedup vs baseline: 1.1513x; 1.1513x over previous
#include <cuda_runtime.h>
#include <cstdint>

// GHMRankingLoss, fused single kernel. Per-thread cp.async.cg (LDGSTS) pipeline.
//
//   result = (1/N) * sum_{b=5..9} max(cnt_b,1)^-0.75 * S_b   (bins 0-4: loss==0)
// u = -t*diff; x = u*(2-t) == 2u + diff (t^2==1). Cumulative register tallies
// C_k = sum_{x>=T_k} u, N_k = #{x>=T_k}, T = {0, ln(6/4), ln(7/3), ln(8/2),
// ln(9/1)}; per-bin values by differencing. FSET -> {0,1}, FFMA/FADD accum.
//
// Memory path: LDGSTS (cp.async.cg, 16B/thread) into a 4-stage x 24KB smem
// ring. Unlike LDG (register-return, ~31KB in-flight/SM cap) and TMA-bulk,
// LDGSTS has NO observed depth cap on B300 -- 3 pending stages * 24KB * 2 CTAs
// = 144KB outstanding per SM. Uniform commit_group every iteration (empty
// groups complete immediately) makes wait_group<ST-2> at iter k guarantee
// stage k is complete. One __syncthreads per stage orders slot reuse.

#define NT 256
#define NB 296               // 2 CTAs/SM * 148 SMs (96KB smem each)
#define K  5
#define ST 4                 // pipeline stages
#define TF 2048              // floats per array per stage (8KB)
#define DSMEM (ST * 3 * TF * 4)   // 96KB dynamic smem

__device__ float2 g_part[K * NB];   // k-major: [k][block] = (C_k, N_k)
__device__ unsigned int g_ticket;   // zero at load; last block resets

__device__ __forceinline__ uint32_t smem_u32(const void* p) {
    return (uint32_t)__cvta_generic_to_shared(p);
}
__device__ __forceinline__ void cp16(uint32_t dst, const void* src) {
    asm volatile("cp.async.cg.shared.global [%0], [%1], 16;"
                 :: "r"(dst), "l"(src) : "memory");
}
__device__ __forceinline__ void cp_commit() {
    asm volatile("cp.async.commit_group;" ::: "memory");
}
template <int N>
__device__ __forceinline__ void cp_wait() {
    asm volatile("cp.async.wait_group %0;" :: "n"(N) : "memory");
}

__device__ __forceinline__ float fset_ge(float x, float T) {
    float r;
    asm("set.ge.f32.f32 %0, %1, %2;" : "=f"(r) : "f"(x), "f"(T));
    return r;   // 1.0f if x >= T else 0.0f
}

__device__ __forceinline__ void ghm_accum(
    float& c0, float& c1, float& c2, float& c3, float& c4,
    float& n0, float& n1, float& n2, float& n3, float& n4,
    float a, float b, float t) {
    float diff = a - b;
    float u = -t * diff;              // == loss whenever u >= 0
    float x = fmaf(2.0f, u, diff);    // == u*(2-t) since t*t == 1
    float r0 = fset_ge(x, 0.0f);
    float r1 = fset_ge(x, 0.40546511f);   // ln(6/4)
    float r2 = fset_ge(x, 0.84729786f);   // ln(7/3)
    float r3 = fset_ge(x, 1.38629436f);   // ln(8/2)
    float r4 = fset_ge(x, 2.19722458f);   // ln(9/1)
    c0 = fmaf(r0, u, c0);  n0 += r0;
    c1 = fmaf(r1, u, c1);  n1 += r1;
    c2 = fmaf(r2, u, c2);  n2 += r2;
    c3 = fmaf(r3, u, c3);  n3 += r3;
    c4 = fmaf(r4, u, c4);  n4 += r4;
}
#define ACC(av, bv, tv) ghm_accum(c0,c1,c2,c3,c4,n0,n1,n2,n3,n4, av, bv, tv)

__global__ void __launch_bounds__(NT, 2)
ghm_fused_k(const float* __restrict__ o1,
            const float* __restrict__ o2,
            const float* __restrict__ tg,
            float* __restrict__ out,
            int n) {
    extern __shared__ __align__(128) float dsm[];   // [ST][3][TF]
    const int tid = threadIdx.x;
    const int bid = blockIdx.x;

    const uint32_t dsm0 = smem_u32(dsm);
    const float4* __restrict__ A = (const float4*)o1;
    const float4* __restrict__ B = (const float4*)o2;
    const float4* __restrict__ T = (const float4*)tg;

    const int ntiles = n / TF;
    const int nmine  = (ntiles > bid) ? (ntiles - bid + NB - 1) / NB : 0;

    // issue one stage: 2 float4 per thread per array (TF/4 = 512 = 2*NT)
    auto issue_tile = [&](int k, int slot) {
        size_t f4 = (size_t)(bid + (size_t)k * NB) * (TF / 4);
        uint32_t d = dsm0 + (uint32_t)slot * (3 * TF * 4);
        cp16(d + tid * 16,                        A + f4 + tid);
        cp16(d + (tid + NT) * 16,                 A + f4 + tid + NT);
        cp16(d + TF * 4 + tid * 16,               B + f4 + tid);
        cp16(d + TF * 4 + (tid + NT) * 16,        B + f4 + tid + NT);
        cp16(d + 2 * TF * 4 + tid * 16,           T + f4 + tid);
        cp16(d + 2 * TF * 4 + (tid + NT) * 16,    T + f4 + tid + NT);
    };

    // prefill ST-1 groups (empty commits keep group arithmetic uniform)
    #pragma unroll
    for (int s = 0; s < ST - 1; s++) {
        if (s < nmine) issue_tile(s, s);
        cp_commit();
    }

    float c0 = 0.f, c1 = 0.f, c2 = 0.f, c3 = 0.f, c4 = 0.f;
    float n0 = 0.f, n1 = 0.f, n2 = 0.f, n3 = 0.f, n4 = 0.f;

    for (int k = 0; k < nmine; k++) {
        cp_wait<ST - 2>();     // group k complete (commits are 1/iteration)
        __syncthreads();       // make all threads' copies visible + order slot reuse

        const float* stg = dsm + (k % ST) * 3 * TF;
        float4 a0 = ((const float4*)stg)[tid];
        float4 a1 = ((const float4*)stg)[tid + NT];
        float4 b0 = ((const float4*)(stg + TF))[tid];
        float4 b1 = ((const float4*)(stg + TF))[tid + NT];
        float4 t0 = ((const float4*)(stg + 2 * TF))[tid];
        float4 t1 = ((const float4*)(stg + 2 * TF))[tid + NT];

        // refill: slot (k+ST-1)%ST == (k-1)%ST, whose reads finished before
        // this iteration's __syncthreads
        int kn = k + ST - 1;
        if (kn < nmine) issue_tile(kn, kn % ST);
        cp_commit();

        ACC(a0.x, b0.x, t0.x);  ACC(a0.y, b0.y, t0.y);
        ACC(a0.z, b0.z, t0.z);  ACC(a0.w, b0.w, t0.w);
        ACC(a1.x, b1.x, t1.x);  ACC(a1.y, b1.y, t1.y);
        ACC(a1.z, b1.z, t1.z);  ACC(a1.w, b1.w, t1.w);
    }
    cp_wait<0>();   // drain (uniform; harmless)

    // tail (n not a multiple of TF): block 0, plain loads
    if (bid == 0) {
        for (int j = ntiles * TF + tid; j < n; j += NT)
            ACC(o1[j], o2[j], tg[j]);
    }

    // ---- block reduce: warp shfl, then cross-warp via smem ----
    float cs[K] = {c0, c1, c2, c3, c4};
    float ns[K] = {n0, n1, n2, n3, n4};
    #pragma unroll
    for (int off = 16; off; off >>= 1) {
        #pragma unroll
        for (int k = 0; k < K; k++) {
            cs[k] += __shfl_down_sync(0xffffffff, cs[k], off);
            ns[k] += __shfl_down_sync(0xffffffff, ns[k], off);
        }
    }

    __shared__ float sC[K][NT / 32], sN[K][NT / 32];
    const int warp = tid >> 5, lane = tid & 31;
    if (lane == 0) {
        #pragma unroll
        for (int k = 0; k < K; k++) { sC[k][warp] = cs[k]; sN[k][warp] = ns[k]; }
    }
    __syncthreads();

    if (tid < K) {
        float c = 0.f, nn = 0.f;
        #pragma unroll
        for (int w = 0; w < NT / 32; w++) { c += sC[tid][w]; nn += sN[tid][w]; }
        g_part[tid * NB + bid] = make_float2(c, nn);
    }

    // ---- ticket: last block finalizes ----
    __shared__ bool isLast;
    __threadfence();
    if (tid == 0) {
        unsigned int v = atomicAdd(&g_ticket, 1u);
        isLast = (v == NB - 1);
    }
    __syncthreads();
    if (!isLast) return;

    __shared__ double ss[K], cc[K];
    if (warp < K) {
        double s = 0.0, c = 0.0;
        for (int j = lane; j < NB; j += 32) {
            float2 p = g_part[warp * NB + j];   // L2-resident
            s += (double)p.x;
            c += (double)p.y;
        }
        #pragma unroll
        for (int off = 16; off; off >>= 1) {
            s += __shfl_down_sync(0xffffffff, s, off);
            c += __shfl_down_sync(0xffffffff, c, off);
        }
        if (lane == 0) { ss[warp] = s; cc[warp] = c; }
    }
    __syncthreads();

    if (tid == 0) {
        double acc = 0.0;
        #pragma unroll
        for (int m = 0; m < K; m++) {
            double Sm  = ss[m] - ((m + 1 < K) ? ss[m + 1] : 0.0);  // bin 5+m loss sum
            double cnt = cc[m] - ((m + 1 < K) ? cc[m + 1] : 0.0);  // bin 5+m count
            double tot = cnt < 1.0 ? 1.0 : cnt;                    // clamp(min=1)
            acc += pow(tot, -0.75) * Sm;                           // w = tot^-alpha
        }
        out[0] = (float)(acc / (double)n);
        g_ticket = 0;                                               // graph-replay safe
    }
}

extern "C" void kernel_launch(void* const* d_in, const int* in_sizes, int n_in,
                              void* d_out, int out_size) {
    const float* o1 = (const float*)d_in[0];
    const float* o2 = (const float*)d_in[1];
    const float* tg = (const float*)d_in[2];
    float* out = (float*)d_out;
    int n = in_sizes[0];

    // idempotent; no allocation. Needed for 96KB dynamic smem.
    cudaFuncSetAttribute(ghm_fused_k, cudaFuncAttributeMaxDynamicSharedMemorySize, DSMEM);
    ghm_fused_k<<<NB, NT, DSMEM>>>(o1, o2, tg, out, n);
}